// round 1
// baseline (speedup 1.0000x reference)
#include <cuda_runtime.h>
#include <cuda_bf16.h>

// out[b,h,i,j] = in[b,h,i,j] + slope[h] * (j - (S-1)),  slope[h] = 2^(-0.5*(h+1))
// Shape: (2, 16, 2048, 2048) fp32. Pure HBM-streaming elementwise add.

static constexpr int SEQ = 2048;            // row length
static constexpr long long ROW_MASK = SEQ - 1;
static constexpr int HEAD_SHIFT = 22;        // 2048*2048 = 2^22 elems per head-plane
static constexpr int HEAD_MASK = 15;         // 16 heads

__global__ void __launch_bounds__(256)
alibi_add_kernel(const float4* __restrict__ in, float4* __restrict__ out,
                 unsigned int n4) {
    unsigned int i = blockIdx.x * blockDim.x + threadIdx.x;
    if (i >= n4) return;

    unsigned long long e = (unsigned long long)i * 4ull;   // element index
    int j = (int)(e & ROW_MASK);                            // column within row
    int h = (int)((e >> HEAD_SHIFT) & HEAD_MASK);           // head index

    float slope = exp2f(-0.5f * (float)(h + 1));
    float base  = (float)(j - (SEQ - 1));                   // distance for lane .x

    float4 v = in[i];
    v.x = fmaf(slope, base,        v.x);
    v.y = fmaf(slope, base + 1.0f, v.y);
    v.z = fmaf(slope, base + 2.0f, v.z);
    v.w = fmaf(slope, base + 3.0f, v.w);
    out[i] = v;
}

extern "C" void kernel_launch(void* const* d_in, const int* in_sizes, int n_in,
                              void* d_out, int out_size) {
    const float4* in = (const float4*)d_in[0];
    float4* out = (float4*)d_out;
    unsigned int n4 = (unsigned int)(out_size / 4);   // 134217728 / 4 = 33554432

    const int block = 256;
    unsigned int grid = (n4 + block - 1) / block;     // 131072 blocks
    alibi_add_kernel<<<grid, block>>>(in, out, n4);
}

// round 2
// speedup vs baseline: 1.0129x; 1.0129x over previous
#include <cuda_runtime.h>
#include <cuda_bf16.h>

// out[b,h,i,j] = in[b,h,i,j] + slope[h] * (j - (S-1)),  slope[h] = 2^(-0.5*(h+1))
// Shape: (2, 16, 2048, 2048) fp32. Pure HBM-streaming elementwise add.
//
// R2: 4 independent float4 loads per thread (front-batched -> MLP_p1=4),
//     streaming cache hints (__ldcs/__stcs), grid 32768 blocks.

static constexpr int SEQ = 2048;             // row length
static constexpr unsigned long long ROW_MASK = SEQ - 1;
static constexpr int HEAD_SHIFT = 22;        // 2048*2048 elems per head-plane
static constexpr int HEAD_MASK = 15;         // 16 heads
static constexpr int VPT = 4;                // float4s per thread

__global__ void __launch_bounds__(256)
alibi_add_kernel(const float4* __restrict__ in, float4* __restrict__ out,
                 unsigned int n4) {
    // Block covers a contiguous chunk of 256*VPT float4s; thread t owns
    // chunk[t], chunk[t+256], chunk[t+512], chunk[t+768]. Fully coalesced.
    unsigned int base = blockIdx.x * (blockDim.x * VPT) + threadIdx.x;

    unsigned int idx[VPT];
    float4 v[VPT];
#pragma unroll
    for (int k = 0; k < VPT; k++) {
        idx[k] = base + k * 256u;
        v[k] = __ldcs(&in[idx[k]]);          // all 4 loads issued before any use
    }

#pragma unroll
    for (int k = 0; k < VPT; k++) {
        unsigned long long e = (unsigned long long)idx[k] * 4ull;
        int j = (int)(e & ROW_MASK);
        int h = (int)((e >> HEAD_SHIFT) & HEAD_MASK);

        float slope = exp2f(-0.5f * (float)(h + 1));
        float d0 = (float)(j - (SEQ - 1));

        float4 r = v[k];
        r.x = fmaf(slope, d0,        r.x);
        r.y = fmaf(slope, d0 + 1.0f, r.y);
        r.z = fmaf(slope, d0 + 2.0f, r.z);
        r.w = fmaf(slope, d0 + 3.0f, r.w);
        __stcs(&out[idx[k]], r);
    }
}

extern "C" void kernel_launch(void* const* d_in, const int* in_sizes, int n_in,
                              void* d_out, int out_size) {
    const float4* in = (const float4*)d_in[0];
    float4* out = (float4*)d_out;
    unsigned int n4 = (unsigned int)(out_size / 4);   // 33554432

    const int block = 256;
    unsigned int grid = n4 / (block * VPT);           // 32768 blocks (exact)
    alibi_add_kernel<<<grid, block>>>(in, out, n4);
}